// round 14
// baseline (speedup 1.0000x reference)
#include <cuda_runtime.h>
#include <cstdint>

#define NCLS   10
#define BLOCK  256
#define NGRID  (152 * 5)     // 5 blocks/SM @ <=51 regs -> exactly one wave
#define NWARPS (BLOCK / 32)

__device__ float2       g_part[NGRID][NCLS];
__device__ unsigned int g_ticket = 0;

// One element:
//  sums:   ind = FSET(tq==c); s[c] = FFMA(ind, sq, s[c])   (10 float regs)
//  counts: 3 packed u32, four 8-bit lanes each (classes 4r..4r+3).
//          key=12 for invalid -> sel=3 matches no counter.
// Per-thread elements <= ~86 so 8-bit lanes cannot overflow.
__device__ __forceinline__ void acc_el(float o, float t, int m,
                                       float* s, unsigned* cnt) {
    float e  = o - t;
    float sq = e * e;
    bool  v  = (m == 1);
    float tq = v ? t : 1e30f;
    #pragma unroll
    for (int c = 0; c < NCLS; c++) {
        float ind;
        asm("set.eq.f32.f32 %0, %1, %2;" : "=f"(ind) : "f"(tq), "f"((float)c));
        s[c] = fmaf(ind, sq, s[c]);
    }
    int key = v ? (int)t : 12;
    unsigned inc = 1u << ((key & 3) * 8);
    int sel = key >> 2;
    #pragma unroll
    for (int r = 0; r < 3; r++)
        if (sel == r) cnt[r] += inc;       // ISETP + predicated IADD
}

__global__ __launch_bounds__(BLOCK, 5) void loss_k(
    const float* __restrict__ outs,
    const float* __restrict__ tgts,
    const int*   __restrict__ mask,
    int n, float* __restrict__ out, int out_size)
{
    __shared__ float2 s_warp[NWARPS][NCLS];
    __shared__ float  le[NCLS];
    __shared__ unsigned int s_ticket;
    const int tid  = threadIdx.x;
    const int lane = tid & 31;
    const int wid  = tid >> 5;

    float    s[NCLS];
    unsigned cnt[3];
    #pragma unroll
    for (int c = 0; c < NCLS; c++) s[c] = 0.0f;
    cnt[0] = cnt[1] = cnt[2] = 0u;

    const int n4 = n >> 2;
    const float4* __restrict__ o4 = reinterpret_cast<const float4*>(outs);
    const float4* __restrict__ t4 = reinterpret_cast<const float4*>(tgts);
    const int4*   __restrict__ m4 = reinterpret_cast<const int4*>(mask);

    const int stride = NGRID * BLOCK;
    int i = blockIdx.x * BLOCK + tid;

    // unroll x2: 6 front-batched LDG.128 per iteration
    for (; i + stride < n4; i += 2 * stride) {
        float4 ov0 = o4[i];
        float4 ov1 = o4[i + stride];
        float4 tv0 = t4[i];
        float4 tv1 = t4[i + stride];
        int4   mv0 = m4[i];
        int4   mv1 = m4[i + stride];
        acc_el(ov0.x, tv0.x, mv0.x, s, cnt);
        acc_el(ov0.y, tv0.y, mv0.y, s, cnt);
        acc_el(ov0.z, tv0.z, mv0.z, s, cnt);
        acc_el(ov0.w, tv0.w, mv0.w, s, cnt);
        acc_el(ov1.x, tv1.x, mv1.x, s, cnt);
        acc_el(ov1.y, tv1.y, mv1.y, s, cnt);
        acc_el(ov1.z, tv1.z, mv1.z, s, cnt);
        acc_el(ov1.w, tv1.w, mv1.w, s, cnt);
    }
    if (i < n4) {
        float4 ov = o4[i];
        float4 tv = t4[i];
        int4   mv = m4[i];
        acc_el(ov.x, tv.x, mv.x, s, cnt);
        acc_el(ov.y, tv.y, mv.y, s, cnt);
        acc_el(ov.z, tv.z, mv.z, s, cnt);
        acc_el(ov.w, tv.w, mv.w, s, cnt);
    }
    if (blockIdx.x == 0) {               // scalar tail (n % 4)
        int j = (n4 << 2) + tid;
        if (j < n) acc_el(outs[j], tgts[j], mask[j], s, cnt);
    }

    // unpack packed counts -> float per class
    float cn[NCLS];
    #pragma unroll
    for (int c = 0; c < NCLS; c++)
        cn[c] = (float)((cnt[c >> 2] >> ((c & 3) * 8)) & 0xFFu);

    // ---- warp shuffle reduction ----
    #pragma unroll
    for (int off = 16; off > 0; off >>= 1) {
        #pragma unroll
        for (int c = 0; c < NCLS; c++) {
            s[c]  += __shfl_down_sync(0xffffffffu, s[c],  off);
            cn[c] += __shfl_down_sync(0xffffffffu, cn[c], off);
        }
    }
    if (lane == 0) {
        #pragma unroll
        for (int c = 0; c < NCLS; c++) s_warp[wid][c] = make_float2(s[c], cn[c]);
    }
    __syncthreads();

    // ---- per-block partial: threads 0..9 combine the warp rows ----
    if (tid < NCLS) {
        float2 p = make_float2(0.0f, 0.0f);
        #pragma unroll
        for (int w = 0; w < NWARPS; w++) {
            float2 v = s_warp[w][tid];
            p.x += v.x; p.y += v.y;
        }
        g_part[blockIdx.x][tid] = p;
    }
    __threadfence();
    __syncthreads();
    if (tid == 0) s_ticket = atomicAdd(&g_ticket, 1u);
    __syncthreads();
    if (s_ticket != (unsigned)(gridDim.x - 1)) return;

    // ---- last block: reduce partials, finalize, write output ----
    __threadfence();

    float2 racc[NCLS];
    #pragma unroll
    for (int c = 0; c < NCLS; c++) racc[c] = make_float2(0.0f, 0.0f);
    for (int j = tid; j < NGRID; j += BLOCK) {
        #pragma unroll
        for (int c = 0; c < NCLS; c++) {
            float2 p = g_part[j][c];
            racc[c].x += p.x;
            racc[c].y += p.y;
        }
    }
    #pragma unroll
    for (int off = 16; off > 0; off >>= 1) {
        #pragma unroll
        for (int c = 0; c < NCLS; c++) {
            racc[c].x += __shfl_down_sync(0xffffffffu, racc[c].x, off);
            racc[c].y += __shfl_down_sync(0xffffffffu, racc[c].y, off);
        }
    }
    if (lane == 0) {
        #pragma unroll
        for (int c = 0; c < NCLS; c++) s_warp[wid][c] = racc[c];
    }
    __syncthreads();

    if (tid < NCLS) {
        float2 tot = make_float2(0.0f, 0.0f);
        #pragma unroll
        for (int w = 0; w < NWARPS; w++) {
            float2 v = s_warp[w][tid];
            tot.x += v.x; tot.y += v.y;
        }
        s_warp[0][tid] = tot;
        le[tid] = (tot.y > 0.0f) ? (tot.x / fmaxf(tot.y, 1.0f)) : 0.0f;
    }
    __syncthreads();

    if (tid == 0) {
        float loss = 0.0f;
        #pragma unroll
        for (int c = 0; c < NCLS; c++) loss += 0.1f * le[c];
        out[0] = loss;
        g_ticket = 0;    // reset for graph replay determinism
    } else if (tid >= 1 && tid <= NCLS) {
        out[tid] = le[tid - 1];                  // loss_each
    } else if (tid >= NCLS + 1 && tid <= 2 * NCLS) {
        out[tid] = s_warp[0][tid - NCLS - 1].y;  // class_n
    } else if (tid < out_size) {
        out[tid] = 0.0f;
    }
}

extern "C" void kernel_launch(void* const* d_in, const int* in_sizes, int n_in,
                              void* d_out, int out_size) {
    const float* outs = (const float*)d_in[0];
    const float* tgts = (const float*)d_in[1];
    const int*   mask = (const int*)d_in[2];
    float* out = (float*)d_out;
    int n = in_sizes[0];

    loss_k<<<NGRID, BLOCK>>>(outs, tgts, mask, n, out, out_size);
}

// round 15
// speedup vs baseline: 1.0593x; 1.0593x over previous
#include <cuda_runtime.h>
#include <cstdint>

#define NCLS   10
#define BLOCK  256
#define NGRID  (152 * 4)     // 4 blocks/SM -> exactly one wave
#define NWARPS (BLOCK / 32)

__device__ float2       g_part[NGRID][NCLS];
__device__ unsigned int g_ticket = 0;

// R13 body (best): un-predicated indicator form.
//   ind  = (tq == c) ? 1.0f : 0.0f   (FSET, alu)
//   sum += ind * sq                   (FFMA, fma)
//   cnt += ind                        (FADD, fma)
// Invalid pixels: tq = 1e30f never matches any class.
__device__ __forceinline__ void acc_el(float o, float t, int m,
                                       float* s, float* cn) {
    float e  = o - t;
    float sq = e * e;
    float tq = (m == 1) ? t : 1e30f;
    #pragma unroll
    for (int c = 0; c < NCLS; c++) {
        float ind;
        asm("set.eq.f32.f32 %0, %1, %2;" : "=f"(ind) : "f"(tq), "f"((float)c));
        s[c]  = fmaf(ind, sq, s[c]);
        cn[c] += ind;
    }
}

__global__ __launch_bounds__(BLOCK, 4) void loss_k(
    const float* __restrict__ outs,
    const float* __restrict__ tgts,
    const int*   __restrict__ mask,
    int n, float* __restrict__ out, int out_size)
{
    __shared__ float2 s_warp[NWARPS][NCLS];
    __shared__ float  le[NCLS];
    __shared__ unsigned int s_ticket;
    const int tid  = threadIdx.x;
    const int lane = tid & 31;
    const int wid  = tid >> 5;

    float s[NCLS], cn[NCLS];
    #pragma unroll
    for (int c = 0; c < NCLS; c++) { s[c] = 0.0f; cn[c] = 0.0f; }

    const int n4 = n >> 2;
    const float4* __restrict__ o4 = reinterpret_cast<const float4*>(outs);
    const float4* __restrict__ t4 = reinterpret_cast<const float4*>(tgts);
    const int4*   __restrict__ m4 = reinterpret_cast<const int4*>(mask);

    const int stride = NGRID * BLOCK;
    int i = blockIdx.x * BLOCK + tid;

    // unroll x3: 9 front-batched LDG.128 per iteration (deep per-warp MLP;
    // issue slots freed by the lean body now cover the longer load batch)
    for (; i + 2 * stride < n4; i += 3 * stride) {
        float4 ov0 = o4[i];
        float4 ov1 = o4[i + stride];
        float4 ov2 = o4[i + 2 * stride];
        float4 tv0 = t4[i];
        float4 tv1 = t4[i + stride];
        float4 tv2 = t4[i + 2 * stride];
        int4   mv0 = m4[i];
        int4   mv1 = m4[i + stride];
        int4   mv2 = m4[i + 2 * stride];
        acc_el(ov0.x, tv0.x, mv0.x, s, cn);
        acc_el(ov0.y, tv0.y, mv0.y, s, cn);
        acc_el(ov0.z, tv0.z, mv0.z, s, cn);
        acc_el(ov0.w, tv0.w, mv0.w, s, cn);
        acc_el(ov1.x, tv1.x, mv1.x, s, cn);
        acc_el(ov1.y, tv1.y, mv1.y, s, cn);
        acc_el(ov1.z, tv1.z, mv1.z, s, cn);
        acc_el(ov1.w, tv1.w, mv1.w, s, cn);
        acc_el(ov2.x, tv2.x, mv2.x, s, cn);
        acc_el(ov2.y, tv2.y, mv2.y, s, cn);
        acc_el(ov2.z, tv2.z, mv2.z, s, cn);
        acc_el(ov2.w, tv2.w, mv2.w, s, cn);
    }
    for (; i < n4; i += stride) {        // remainder float4s
        float4 ov = o4[i];
        float4 tv = t4[i];
        int4   mv = m4[i];
        acc_el(ov.x, tv.x, mv.x, s, cn);
        acc_el(ov.y, tv.y, mv.y, s, cn);
        acc_el(ov.z, tv.z, mv.z, s, cn);
        acc_el(ov.w, tv.w, mv.w, s, cn);
    }
    if (blockIdx.x == 0) {               // scalar tail (n % 4)
        int j = (n4 << 2) + tid;
        if (j < n) acc_el(outs[j], tgts[j], mask[j], s, cn);
    }

    // ---- warp shuffle reduction ----
    #pragma unroll
    for (int off = 16; off > 0; off >>= 1) {
        #pragma unroll
        for (int c = 0; c < NCLS; c++) {
            s[c]  += __shfl_down_sync(0xffffffffu, s[c],  off);
            cn[c] += __shfl_down_sync(0xffffffffu, cn[c], off);
        }
    }
    if (lane == 0) {
        #pragma unroll
        for (int c = 0; c < NCLS; c++) s_warp[wid][c] = make_float2(s[c], cn[c]);
    }
    __syncthreads();

    // ---- per-block partial: threads 0..9 combine the warp rows ----
    if (tid < NCLS) {
        float2 p = make_float2(0.0f, 0.0f);
        #pragma unroll
        for (int w = 0; w < NWARPS; w++) {
            float2 v = s_warp[w][tid];
            p.x += v.x; p.y += v.y;
        }
        g_part[blockIdx.x][tid] = p;
    }
    __threadfence();
    __syncthreads();
    if (tid == 0) s_ticket = atomicAdd(&g_ticket, 1u);
    __syncthreads();
    if (s_ticket != (unsigned)(gridDim.x - 1)) return;

    // ---- last block: reduce partials, finalize, write output ----
    __threadfence();

    float2 racc[NCLS];
    #pragma unroll
    for (int c = 0; c < NCLS; c++) racc[c] = make_float2(0.0f, 0.0f);
    for (int j = tid; j < NGRID; j += BLOCK) {
        #pragma unroll
        for (int c = 0; c < NCLS; c++) {
            float2 p = g_part[j][c];
            racc[c].x += p.x;
            racc[c].y += p.y;
        }
    }
    #pragma unroll
    for (int off = 16; off > 0; off >>= 1) {
        #pragma unroll
        for (int c = 0; c < NCLS; c++) {
            racc[c].x += __shfl_down_sync(0xffffffffu, racc[c].x, off);
            racc[c].y += __shfl_down_sync(0xffffffffu, racc[c].y, off);
        }
    }
    if (lane == 0) {
        #pragma unroll
        for (int c = 0; c < NCLS; c++) s_warp[wid][c] = racc[c];
    }
    __syncthreads();

    if (tid < NCLS) {
        float2 tot = make_float2(0.0f, 0.0f);
        #pragma unroll
        for (int w = 0; w < NWARPS; w++) {
            float2 v = s_warp[w][tid];
            tot.x += v.x; tot.y += v.y;
        }
        s_warp[0][tid] = tot;
        le[tid] = (tot.y > 0.0f) ? (tot.x / fmaxf(tot.y, 1.0f)) : 0.0f;
    }
    __syncthreads();

    if (tid == 0) {
        float loss = 0.0f;
        #pragma unroll
        for (int c = 0; c < NCLS; c++) loss += 0.1f * le[c];
        out[0] = loss;
        g_ticket = 0;    // reset for graph replay determinism
    } else if (tid >= 1 && tid <= NCLS) {
        out[tid] = le[tid - 1];                  // loss_each
    } else if (tid >= NCLS + 1 && tid <= 2 * NCLS) {
        out[tid] = s_warp[0][tid - NCLS - 1].y;  // class_n
    } else if (tid < out_size) {
        out[tid] = 0.0f;
    }
}

extern "C" void kernel_launch(void* const* d_in, const int* in_sizes, int n_in,
                              void* d_out, int out_size) {
    const float* outs = (const float*)d_in[0];
    const float* tgts = (const float*)d_in[1];
    const int*   mask = (const int*)d_in[2];
    float* out = (float*)d_out;
    int n = in_sizes[0];

    loss_k<<<NGRID, BLOCK>>>(outs, tgts, mask, n, out, out_size);
}

// round 16
// speedup vs baseline: 1.1173x; 1.0548x over previous
#include <cuda_runtime.h>
#include <cstdint>

#define NCLS   10
#define BLOCK  256
#define NGRID  (152 * 4)     // 4 blocks/SM -> exactly one wave
#define NWARPS (BLOCK / 32)

__device__ float        g_sum[NCLS];     // .bss zero-init; last block resets
__device__ float        g_cnt[NCLS];
__device__ unsigned int g_ticket = 0;

// R13 body (best): un-predicated indicator form.
//   ind  = (tq == c) ? 1.0f : 0.0f   (FSET, alu)
//   sum += ind * sq                   (FFMA, fma)
//   cnt += ind                        (FADD, fma)
// Invalid pixels: tq = 1e30f never matches any class.
__device__ __forceinline__ void acc_el(float o, float t, int m,
                                       float* s, float* cn) {
    float e  = o - t;
    float sq = e * e;
    float tq = (m == 1) ? t : 1e30f;
    #pragma unroll
    for (int c = 0; c < NCLS; c++) {
        float ind;
        asm("set.eq.f32.f32 %0, %1, %2;" : "=f"(ind) : "f"(tq), "f"((float)c));
        s[c]  = fmaf(ind, sq, s[c]);
        cn[c] += ind;
    }
}

__global__ __launch_bounds__(BLOCK, 4) void loss_k(
    const float* __restrict__ outs,
    const float* __restrict__ tgts,
    const int*   __restrict__ mask,
    int n, float* __restrict__ out, int out_size)
{
    __shared__ float2 s_warp[NWARPS][NCLS];
    __shared__ float  le[NCLS];
    __shared__ unsigned int s_ticket;
    const int tid  = threadIdx.x;
    const int lane = tid & 31;
    const int wid  = tid >> 5;

    float s[NCLS], cn[NCLS];
    #pragma unroll
    for (int c = 0; c < NCLS; c++) { s[c] = 0.0f; cn[c] = 0.0f; }

    const int n4 = n >> 2;
    const float4* __restrict__ o4 = reinterpret_cast<const float4*>(outs);
    const float4* __restrict__ t4 = reinterpret_cast<const float4*>(tgts);
    const int4*   __restrict__ m4 = reinterpret_cast<const int4*>(mask);

    const int stride = NGRID * BLOCK;
    int i = blockIdx.x * BLOCK + tid;

    // unroll x2: 6 front-batched streaming LDG.128 per iteration
    for (; i + stride < n4; i += 2 * stride) {
        float4 ov0 = __ldcs(o4 + i);
        float4 ov1 = __ldcs(o4 + i + stride);
        float4 tv0 = __ldcs(t4 + i);
        float4 tv1 = __ldcs(t4 + i + stride);
        int4   mv0 = __ldcs(m4 + i);
        int4   mv1 = __ldcs(m4 + i + stride);
        acc_el(ov0.x, tv0.x, mv0.x, s, cn);
        acc_el(ov0.y, tv0.y, mv0.y, s, cn);
        acc_el(ov0.z, tv0.z, mv0.z, s, cn);
        acc_el(ov0.w, tv0.w, mv0.w, s, cn);
        acc_el(ov1.x, tv1.x, mv1.x, s, cn);
        acc_el(ov1.y, tv1.y, mv1.y, s, cn);
        acc_el(ov1.z, tv1.z, mv1.z, s, cn);
        acc_el(ov1.w, tv1.w, mv1.w, s, cn);
    }
    if (i < n4) {
        float4 ov = __ldcs(o4 + i);
        float4 tv = __ldcs(t4 + i);
        int4   mv = __ldcs(m4 + i);
        acc_el(ov.x, tv.x, mv.x, s, cn);
        acc_el(ov.y, tv.y, mv.y, s, cn);
        acc_el(ov.z, tv.z, mv.z, s, cn);
        acc_el(ov.w, tv.w, mv.w, s, cn);
    }
    if (blockIdx.x == 0) {               // scalar tail (n % 4)
        int j = (n4 << 2) + tid;
        if (j < n) acc_el(outs[j], tgts[j], mask[j], s, cn);
    }

    // ---- warp shuffle reduction ----
    #pragma unroll
    for (int off = 16; off > 0; off >>= 1) {
        #pragma unroll
        for (int c = 0; c < NCLS; c++) {
            s[c]  += __shfl_down_sync(0xffffffffu, s[c],  off);
            cn[c] += __shfl_down_sync(0xffffffffu, cn[c], off);
        }
    }
    if (lane == 0) {
        #pragma unroll
        for (int c = 0; c < NCLS; c++) s_warp[wid][c] = make_float2(s[c], cn[c]);
    }
    __syncthreads();

    // ---- per-block partial -> 20 global float atomics (parallel LTS slots) ----
    if (tid < NCLS) {
        float ps = 0.0f;
        #pragma unroll
        for (int w = 0; w < NWARPS; w++) ps += s_warp[w][tid].x;
        atomicAdd(&g_sum[tid], ps);
    } else if (tid >= 32 && tid < 32 + NCLS) {
        int c = tid - 32;
        float pc = 0.0f;
        #pragma unroll
        for (int w = 0; w < NWARPS; w++) pc += s_warp[w][c].y;
        atomicAdd(&g_cnt[c], pc);
    }
    __threadfence();
    __syncthreads();
    if (tid == 0) s_ticket = atomicAdd(&g_ticket, 1u);
    __syncthreads();
    if (s_ticket != (unsigned)(gridDim.x - 1)) return;

    // ---- last block: read 20 totals, finalize, reset, write output ----
    __threadfence();

    __shared__ float tot_n[NCLS];
    if (tid < NCLS) {
        float ts = g_sum[tid];
        float tn = g_cnt[tid];
        tot_n[tid] = tn;
        le[tid] = (tn > 0.0f) ? (ts / fmaxf(tn, 1.0f)) : 0.0f;
        g_sum[tid] = 0.0f;               // reset for next graph replay
        g_cnt[tid] = 0.0f;
    }
    __syncthreads();

    if (tid == 0) {
        float loss = 0.0f;
        #pragma unroll
        for (int c = 0; c < NCLS; c++) loss += 0.1f * le[c];
        out[0] = loss;
        g_ticket = 0;                    // reset ticket
    } else if (tid >= 1 && tid <= NCLS) {
        out[tid] = le[tid - 1];          // loss_each
    } else if (tid >= NCLS + 1 && tid <= 2 * NCLS) {
        out[tid] = tot_n[tid - NCLS - 1];// class_n
    } else if (tid < out_size) {
        out[tid] = 0.0f;
    }
}

extern "C" void kernel_launch(void* const* d_in, const int* in_sizes, int n_in,
                              void* d_out, int out_size) {
    const float* outs = (const float*)d_in[0];
    const float* tgts = (const float*)d_in[1];
    const int*   mask = (const int*)d_in[2];
    float* out = (float*)d_out;
    int n = in_sizes[0];

    loss_k<<<NGRID, BLOCK>>>(outs, tgts, mask, n, out, out_size);
}